// round 2
// baseline (speedup 1.0000x reference)
#include <cuda_runtime.h>
#include <cstdint>

#define KBINS 32768
#define HW 262144
#define MAXB 64

// scratch (allocation-free rule: __device__ globals)
__device__ unsigned int g_hist[2 * MAXB * KBINS];   // 16 MB: counts per (segment, bin)
__device__ signed char  g_sign[MAXB * KBINS];       // 2 MB: per-bin sign per batch
__device__ double       g_part2[MAXB];              // count-part partials (per batch)
__device__ double       g_part3[4 * MAXB];          // value-part partials (per CTA)

__device__ __forceinline__ int binOf(float v) {
    int b = (int)(v * 32768.0f);       // exact scale by 2^15; v in [0,1)
    b = b < 0 ? 0 : b;
    b = b > (KBINS - 1) ? (KBINS - 1) : b;
    return b;
}

__device__ __forceinline__ double blockReduceD(double v) {
    __shared__ double sp[32];
    int lane = threadIdx.x & 31, wid = threadIdx.x >> 5;
#pragma unroll
    for (int o = 16; o; o >>= 1) v += __shfl_down_sync(0xffffffffu, v, o);
    if (lane == 0) sp[wid] = v;
    __syncthreads();
    int nw = (blockDim.x + 31) >> 5;
    if (wid == 0) {
        v = (lane < nw) ? sp[lane] : 0.0;
#pragma unroll
        for (int o = 16; o; o >>= 1) v += __shfl_down_sync(0xffffffffu, v, o);
    }
    return v;  // valid in thread 0
}

// ---------------------------------------------------------------------------
// K1: per-segment count histogram in shared memory (128 KB dynamic smem)
// grid = 2*B, block = 1024
// ---------------------------------------------------------------------------
__global__ void k_hist(const float* __restrict__ x, const float* __restrict__ y) {
    extern __shared__ unsigned int sh[];
    int seg = blockIdx.x;  // batch = seg>>1, isY = seg&1
    const float* src = ((seg & 1) ? y : x) + (size_t)(seg >> 1) * HW;
    for (int i = threadIdx.x; i < KBINS; i += blockDim.x) sh[i] = 0u;
    __syncthreads();
    const float4* p = (const float4*)src;
    for (int i = threadIdx.x; i < HW / 4; i += blockDim.x) {
        float4 v = p[i];
        atomicAdd(&sh[binOf(v.x)], 1u);
        atomicAdd(&sh[binOf(v.y)], 1u);
        atomicAdd(&sh[binOf(v.z)], 1u);
        atomicAdd(&sh[binOf(v.w)], 1u);
    }
    __syncthreads();
    unsigned int* g = g_hist + (size_t)seg * KBINS;
    for (int i = threadIdx.x; i < KBINS; i += blockDim.x) g[i] = sh[i];
}

// ---------------------------------------------------------------------------
// K2: per-batch scan over bins. D_in = prefix(Hx-Hy). Accumulates
//   s * Delta * (D_in + d*(k+1))   (the count part of the bin integral)
// and stores the per-bin sign for K3.
// grid = B, block = 1024
// ---------------------------------------------------------------------------
__global__ void k_scan() {
    int b = blockIdx.x;
    const unsigned int* hx = g_hist + (size_t)(2 * b) * KBINS;
    const unsigned int* hy = g_hist + (size_t)(2 * b + 1) * KBINS;
    __shared__ int wtot[32];
    int lane = threadIdx.x & 31, wid = threadIdx.x >> 5;
    long long carry = 0;
    double acc = 0.0;
    const double DELTA = 1.0 / 32768.0;
    for (int it = 0; it < KBINS / 1024; ++it) {
        int k = it * 1024 + threadIdx.x;
        int d = (int)hx[k] - (int)hy[k];
        // inclusive warp scan of d
        int s = d;
#pragma unroll
        for (int o = 1; o < 32; o <<= 1) {
            int t = __shfl_up_sync(0xffffffffu, s, o);
            if (lane >= o) s += t;
        }
        if (lane == 31) wtot[wid] = s;
        __syncthreads();
        if (wid == 0) {
            int w = wtot[lane];
#pragma unroll
            for (int o = 1; o < 32; o <<= 1) {
                int t = __shfl_up_sync(0xffffffffu, w, o);
                if (lane >= o) w += t;
            }
            wtot[lane] = w;  // inclusive prefix of warp totals
        }
        __syncthreads();
        long long Din = carry + (long long)(wid > 0 ? wtot[wid - 1] : 0) + (long long)(s - d);
        int blockTot = wtot[31];
        int sgn = (2 * Din + (long long)d >= 0) ? 1 : -1;
        acc += (double)sgn * DELTA * ((double)Din + (double)d * (double)(k + 1));
        g_sign[(size_t)b * KBINS + k] = (signed char)sgn;
        carry += (long long)blockTot;
        __syncthreads();  // protect wtot reuse next iteration
    }
    double tot = blockReduceD(acc);
    if (threadIdx.x == 0) g_part2[b] = tot;
}

// ---------------------------------------------------------------------------
// K3: signed value sums. x elements contribute -s*v, y elements +s*v
// (the  -Sx + Sy  part of the bin integral). Sign table cached in smem.
// grid = 4*B (each CTA = half a segment), block = 1024
// ---------------------------------------------------------------------------
__global__ void k_signed(const float* __restrict__ x, const float* __restrict__ y) {
    int cta = blockIdx.x;
    int seg = cta >> 1;
    int half = cta & 1;
    int b = seg >> 1;
    int isY = seg & 1;
    __shared__ signed char ss[KBINS];
    const int4* sp = (const int4*)(g_sign + (size_t)b * KBINS);
    int4* sd = (int4*)ss;
    for (int i = threadIdx.x; i < KBINS / 16; i += blockDim.x) sd[i] = sp[i];
    __syncthreads();
    const float* src = (isY ? y : x) + (size_t)b * HW + (size_t)half * (HW / 2);
    const float4* p = (const float4*)src;
    double acc = 0.0;
    for (int i = threadIdx.x; i < HW / 8; i += blockDim.x) {
        float4 v = p[i];
        float t = (float)ss[binOf(v.x)] * v.x + (float)ss[binOf(v.y)] * v.y +
                  (float)ss[binOf(v.z)] * v.z + (float)ss[binOf(v.w)] * v.w;
        acc += (double)t;
    }
    double tot = blockReduceD(acc);
    if (threadIdx.x == 0) g_part3[cta] = isY ? tot : -tot;
}

// ---------------------------------------------------------------------------
// K4: final reduction of all partials -> float scalar
// ---------------------------------------------------------------------------
__global__ void k_final(float* __restrict__ out, int B) {
    double v = 0.0;
    for (int i = threadIdx.x; i < B; i += blockDim.x) v += g_part2[i];
    for (int i = threadIdx.x; i < 4 * B; i += blockDim.x) v += g_part3[i];
    double tot = blockReduceD(v);
    if (threadIdx.x == 0) out[0] = (float)tot;
}

extern "C" void kernel_launch(void* const* d_in, const int* in_sizes, int n_in,
                              void* d_out, int out_size) {
    const float* x = (const float*)d_in[0];
    const float* y = (const float*)d_in[1];
    int B = in_sizes[0] / HW;
    if (B > MAXB) B = MAXB;

    // opt-in to 128 KB dynamic smem for the histogram kernel (idempotent)
    cudaFuncSetAttribute(k_hist, cudaFuncAttributeMaxDynamicSharedMemorySize,
                         KBINS * (int)sizeof(unsigned int));

    k_hist<<<2 * B, 1024, KBINS * sizeof(unsigned int)>>>(x, y);
    k_scan<<<B, 1024>>>();
    k_signed<<<4 * B, 1024>>>(x, y);
    k_final<<<1, 256>>>((float*)d_out, B);
}

// round 3
// speedup vs baseline: 1.6372x; 1.6372x over previous
#include <cuda_runtime.h>
#include <cstdint>

#define KB2   16384          // bins
#define HW    262144         // H*W per batch
#define MAXB  64
#define NPART 4              // histogram CTAs per batch

// scratch (allocation-free rule: __device__ globals)
__device__ unsigned int g_part[MAXB * NPART * KB2];   // 16 MB partial packed hists

// packed accumulator: T = d*2^22 + S,  S = sum(+-round(v*2^14))
__device__ __forceinline__ int binOf(float v) {
    int b = (int)(v * 16384.0f);        // v in [0,1): truncation == floor
    b = b < 0 ? 0 : b;
    b = b > (KB2 - 1) ? (KB2 - 1) : b;
    return b;
}
__device__ __forceinline__ unsigned int encP(float v) {
    return (1u << 22) + (unsigned int)__float2int_rn(v * 16384.0f);
}

__device__ __forceinline__ double blockReduceD(double v) {
    __shared__ double sp[32];
    int lane = threadIdx.x & 31, wid = threadIdx.x >> 5;
#pragma unroll
    for (int o = 16; o; o >>= 1) v += __shfl_down_sync(0xffffffffu, v, o);
    if (lane == 0) sp[wid] = v;
    __syncthreads();
    int nw = (blockDim.x + 31) >> 5;
    if (wid == 0) {
        v = (lane < nw) ? sp[lane] : 0.0;
#pragma unroll
        for (int o = 16; o; o >>= 1) v += __shfl_down_sync(0xffffffffu, v, o);
    }
    return v;  // valid in thread 0
}

// ---------------------------------------------------------------------------
// K1: packed signed histogram partials.
// grid = NPART*B (each CTA: one quarter of x AND y of one batch), block = 1024
// smem = 64 KB dynamic (u32[16384])
// x contributes +enc(v), y contributes -enc(v)  ->  per-bin (d, Sx-Sy) packed.
// ---------------------------------------------------------------------------
__global__ void k_hist(const float* __restrict__ x, const float* __restrict__ y) {
    extern __shared__ unsigned int sh[];
    int cta = blockIdx.x;
    int b = cta >> 2, q = cta & 3;
    for (int i = threadIdx.x; i < KB2; i += blockDim.x) sh[i] = 0u;
    __syncthreads();
    const int QE = HW / NPART;  // 65536 elements of each of x,y
    const float4* px = (const float4*)(x + (size_t)b * HW + (size_t)q * QE);
    const float4* py = (const float4*)(y + (size_t)b * HW + (size_t)q * QE);
    for (int i = threadIdx.x; i < QE / 4; i += blockDim.x) {
        float4 vx = px[i];
        float4 vy = py[i];
        atomicAdd(&sh[binOf(vx.x)], encP(vx.x));
        atomicAdd(&sh[binOf(vy.x)], (unsigned int)(-(int)encP(vy.x)));
        atomicAdd(&sh[binOf(vx.y)], encP(vx.y));
        atomicAdd(&sh[binOf(vy.y)], (unsigned int)(-(int)encP(vy.y)));
        atomicAdd(&sh[binOf(vx.z)], encP(vx.z));
        atomicAdd(&sh[binOf(vy.z)], (unsigned int)(-(int)encP(vy.z)));
        atomicAdd(&sh[binOf(vx.w)], encP(vx.w));
        atomicAdd(&sh[binOf(vy.w)], (unsigned int)(-(int)encP(vy.w)));
    }
    __syncthreads();
    unsigned int* g = g_part + (size_t)cta * KB2;
    for (int i = threadIdx.x; i < KB2; i += blockDim.x) g[i] = sh[i];
}

// ---------------------------------------------------------------------------
// K2: per-batch combine partials + scan + exact per-bin |integral|.
//   integ_k = D_in*Delta + d_k*(k+1)*Delta - S_k/2^14   ;  acc += |integ_k|
// grid = B, block = 1024. atomicAdd result into out[0].
// ---------------------------------------------------------------------------
__global__ void k_scan(float* __restrict__ out) {
    int b = blockIdx.x;
    const unsigned int* p = g_part + (size_t)b * NPART * KB2;
    __shared__ int wtot[32];
    int lane = threadIdx.x & 31, wid = threadIdx.x >> 5;
    long long carry = 0;
    double acc = 0.0;
    const double DELTA = 1.0 / 16384.0;
    const double VSCL  = 1.0 / 16384.0;   // value field scale 2^-14
    for (int it = 0; it < KB2 / 1024; ++it) {
        int k = it * 1024 + threadIdx.x;
        int T = (int)(p[k] + p[KB2 + k] + p[2 * KB2 + k] + p[3 * KB2 + k]);
        int d = (T + (1 << 21)) >> 22;        // count diff Hx-Hy
        int S = T - (d << 22);                // scaled Sx-Sy
        // inclusive warp scan of d
        int s = d;
#pragma unroll
        for (int o = 1; o < 32; o <<= 1) {
            int t = __shfl_up_sync(0xffffffffu, s, o);
            if (lane >= o) s += t;
        }
        if (lane == 31) wtot[wid] = s;
        __syncthreads();
        if (wid == 0) {
            int w = wtot[lane];
#pragma unroll
            for (int o = 1; o < 32; o <<= 1) {
                int t = __shfl_up_sync(0xffffffffu, w, o);
                if (lane >= o) w += t;
            }
            wtot[lane] = w;
        }
        __syncthreads();
        long long Din = carry + (long long)(wid > 0 ? wtot[wid - 1] : 0) + (long long)(s - d);
        int blockTot = wtot[31];
        double integ = (double)Din * DELTA + (double)d * (double)(k + 1) * DELTA
                     - (double)S * VSCL;
        acc += fabs(integ);
        carry += (long long)blockTot;
        __syncthreads();  // protect wtot for next iteration
    }
    double tot = blockReduceD(acc);
    if (threadIdx.x == 0) atomicAdd(out, (float)tot);
}

extern "C" void kernel_launch(void* const* d_in, const int* in_sizes, int n_in,
                              void* d_out, int out_size) {
    const float* x = (const float*)d_in[0];
    const float* y = (const float*)d_in[1];
    int B = in_sizes[0] / HW;
    if (B > MAXB) B = MAXB;

    cudaFuncSetAttribute(k_hist, cudaFuncAttributeMaxDynamicSharedMemorySize,
                         KB2 * (int)sizeof(unsigned int));

    cudaMemsetAsync(d_out, 0, sizeof(float));
    k_hist<<<NPART * B, 1024, KB2 * sizeof(unsigned int)>>>(x, y);
    k_scan<<<B, 1024>>>((float*)d_out);
}

// round 4
// speedup vs baseline: 3.0226x; 1.8462x over previous
#include <cuda_runtime.h>
#include <cstdint>

#define KB2   16384          // bins
#define HW    262144         // H*W per batch
#define MAXB  64
#define NPART 4              // histogram CTAs per batch
#define NCH   16             // prefix chunks per batch
#define CHB   (KB2 / NCH)    // 1024 bins per chunk

// scratch (allocation-free rule: __device__ globals)
__device__ unsigned int g_hist[MAXB * KB2];   // 4 MB combined packed hist
__device__ int          g_csum[MAXB * NCH];   // per-chunk d sums

// packed accumulator: T = d*2^22 + S,  S = sum(+-round(v*2^14))
__device__ __forceinline__ int binOf(float v) {
    int b = (int)(v * 16384.0f);        // v in [0,1): truncation == floor
    b = b < 0 ? 0 : b;
    b = b > (KB2 - 1) ? (KB2 - 1) : b;
    return b;
}
__device__ __forceinline__ unsigned int encP(float v) {
    return (1u << 22) + (unsigned int)__float2int_rn(v * 16384.0f);
}
__device__ __forceinline__ int decD(unsigned int t) {
    return ((int)t + (1 << 21)) >> 22;   // count field (round to nearest)
}

// ---------------------------------------------------------------------------
// K1: packed signed histogram, combined across partial CTAs with global
// atomics; also emits per-chunk d-sums for the decoupled prefix.
// grid = NPART*B, block = 1024, smem = 64 KB dynamic
// ---------------------------------------------------------------------------
__global__ void k_hist(const float* __restrict__ x, const float* __restrict__ y) {
    extern __shared__ unsigned int sh[];
    __shared__ int sc[NCH];
    int cta = blockIdx.x;
    int b = cta >> 2, q = cta & 3;
    for (int i = threadIdx.x; i < KB2; i += blockDim.x) sh[i] = 0u;
    if (threadIdx.x < NCH) sc[threadIdx.x] = 0;
    __syncthreads();

    const int QE = HW / NPART;  // 65536 elements of each of x,y
    const float4* px = (const float4*)(x + (size_t)b * HW + (size_t)q * QE);
    const float4* py = (const float4*)(y + (size_t)b * HW + (size_t)q * QE);
    for (int i = threadIdx.x; i < QE / 4; i += blockDim.x) {
        float4 vx = px[i];
        float4 vy = py[i];
        atomicAdd(&sh[binOf(vx.x)], encP(vx.x));
        atomicAdd(&sh[binOf(vy.x)], (unsigned int)(-(int)encP(vy.x)));
        atomicAdd(&sh[binOf(vx.y)], encP(vx.y));
        atomicAdd(&sh[binOf(vy.y)], (unsigned int)(-(int)encP(vy.y)));
        atomicAdd(&sh[binOf(vx.z)], encP(vx.z));
        atomicAdd(&sh[binOf(vy.z)], (unsigned int)(-(int)encP(vy.z)));
        atomicAdd(&sh[binOf(vx.w)], encP(vx.w));
        atomicAdd(&sh[binOf(vy.w)], (unsigned int)(-(int)encP(vy.w)));
    }
    __syncthreads();

    // write-out: combine into global hist + per-chunk d sums
    unsigned int* g = g_hist + (size_t)b * KB2;
    int lane = threadIdx.x & 31;
#pragma unroll
    for (int j = 0; j < NCH; ++j) {
        int i = threadIdx.x + j * 1024;     // bin i lies in chunk j (blockDim==1024)
        unsigned int t = sh[i];
        if (t) atomicAdd(&g[i], t);
        int d = decD(t);
#pragma unroll
        for (int o = 16; o; o >>= 1) d += __shfl_down_sync(0xffffffffu, d, o);
        if (lane == 0 && d != 0) atomicAdd(&sc[j], d);
    }
    __syncthreads();
    if (threadIdx.x < NCH && sc[threadIdx.x] != 0)
        atomicAdd(&g_csum[b * NCH + threadIdx.x], sc[threadIdx.x]);
}

// ---------------------------------------------------------------------------
// K2: fully parallel per-chunk scan. Exact integer per-bin integral:
//   integ_k * 2^14 = Din + d_k*(k+1) - S_k     (all integers)
// grid = B*NCH, block = 256 (one uint4 = 4 bins per thread)
// ---------------------------------------------------------------------------
__global__ void k_scan(float* __restrict__ out) {
    int cta = blockIdx.x;
    int b = cta >> 4, ch = cta & (NCH - 1);
    const uint4* p = (const uint4*)(g_hist + (size_t)b * KB2 + ch * CHB);
    uint4 T = p[threadIdx.x];

    int d0 = decD(T.x), d1 = decD(T.y), d2 = decD(T.z), d3 = decD(T.w);
    int S0 = (int)T.x - (d0 << 22);
    int S1 = (int)T.y - (d1 << 22);
    int S2 = (int)T.z - (d2 << 22);
    int S3 = (int)T.w - (d3 << 22);
    int tsum = d0 + d1 + d2 + d3;

    // carry into this chunk = sum of earlier chunks' d totals (same batch)
    int carry = 0;
    for (int qq = 0; qq < ch; ++qq) carry += g_csum[b * NCH + qq];

    // block exclusive scan of per-thread tsum (256 threads = 8 warps)
    int lane = threadIdx.x & 31, wid = threadIdx.x >> 5;
    int s = tsum;
#pragma unroll
    for (int o = 1; o < 32; o <<= 1) {
        int t = __shfl_up_sync(0xffffffffu, s, o);
        if (lane >= o) s += t;
    }
    __shared__ int wt[8];
    if (lane == 31) wt[wid] = s;
    __syncthreads();
    if (wid == 0) {
        int w = (lane < 8) ? wt[lane] : 0;
#pragma unroll
        for (int o = 1; o < 8; o <<= 1) {
            int t = __shfl_up_sync(0xffffffffu, w, o);
            if (lane >= o) w += t;
        }
        if (lane < 8) wt[lane] = w;
    }
    __syncthreads();
    int excl = (wid ? wt[wid - 1] : 0) + (s - tsum);

    long long Din = (long long)carry + excl;
    int kg = ch * CHB + threadIdx.x * 4;   // global bin index of first of 4

    long long acc = 0;
    long long v;
    v = Din + (long long)d0 * (kg + 1) - S0;  acc += v < 0 ? -v : v;  Din += d0;
    v = Din + (long long)d1 * (kg + 2) - S1;  acc += v < 0 ? -v : v;  Din += d1;
    v = Din + (long long)d2 * (kg + 3) - S2;  acc += v < 0 ? -v : v;  Din += d2;
    v = Din + (long long)d3 * (kg + 4) - S3;  acc += v < 0 ? -v : v;

    // block reduce acc (int64)
#pragma unroll
    for (int o = 16; o; o >>= 1) acc += __shfl_down_sync(0xffffffffu, acc, o);
    __shared__ long long wr[8];
    if (lane == 0) wr[wid] = acc;
    __syncthreads();
    if (wid == 0) {
        acc = (lane < 8) ? wr[lane] : 0;
#pragma unroll
        for (int o = 4; o; o >>= 1) acc += __shfl_down_sync(0xffffffffu, acc, o);
        if (lane == 0) atomicAdd(out, (float)((double)acc * (1.0 / 16384.0)));
    }
}

extern "C" void kernel_launch(void* const* d_in, const int* in_sizes, int n_in,
                              void* d_out, int out_size) {
    const float* x = (const float*)d_in[0];
    const float* y = (const float*)d_in[1];
    int B = in_sizes[0] / HW;
    if (B > MAXB) B = MAXB;

    cudaFuncSetAttribute(k_hist, cudaFuncAttributeMaxDynamicSharedMemorySize,
                         KB2 * (int)sizeof(unsigned int));

    void* hist_ptr = nullptr;
    void* csum_ptr = nullptr;
    cudaGetSymbolAddress(&hist_ptr, g_hist);
    cudaGetSymbolAddress(&csum_ptr, g_csum);

    cudaMemsetAsync(d_out, 0, sizeof(float));
    cudaMemsetAsync(hist_ptr, 0, (size_t)B * KB2 * sizeof(unsigned int));
    cudaMemsetAsync(csum_ptr, 0, (size_t)B * NCH * sizeof(int));

    k_hist<<<NPART * B, 1024, KB2 * sizeof(unsigned int)>>>(x, y);
    k_scan<<<B * NCH, 256>>>((float*)d_out);
}

// round 5
// speedup vs baseline: 4.4296x; 1.4655x over previous
#include <cuda_runtime.h>
#include <cstdint>

#define KB    8192           // bins (bin = S>>1, S = round(v*2^14))
#define NCH   16             // prefix chunks per batch
#define CHB   (KB / NCH)     // 512 bins per chunk
#define NPART 4              // histogram CTAs per batch
#define HW    262144         // H*W per batch
#define MAXB  64

// scratch (allocation-free rule: __device__ globals)
__device__ unsigned int g_part[MAXB * NPART * KB];    // 8 MB packed partials
__device__ int          g_csum[MAXB * NCH * NPART];   // per-chunk d sums, [b][ch][part]

// packed word: T = d*2^22 + S_signed
__device__ __forceinline__ int decD(unsigned int t) {
    return ((int)t + (1 << 21)) >> 22;
}
__device__ __forceinline__ unsigned int quantS(float v) {
    int S = __float2int_rn(v * 16384.0f);
    return (unsigned int)min(S, 16383);
}

// ---------------------------------------------------------------------------
// K1: packed signed histogram partials (plain stores) + per-chunk d sums.
// grid = NPART*B, block = 1024, smem = 32 KB static
// ---------------------------------------------------------------------------
__global__ void __launch_bounds__(1024, 2) k_hist(const float* __restrict__ x,
                                                  const float* __restrict__ y) {
    __shared__ unsigned int sh[KB];
    __shared__ int sc[NCH];
    int cta = blockIdx.x;
    int b = cta >> 2, q = cta & 3;
    uint4* s4 = (uint4*)sh;
    for (int i = threadIdx.x; i < KB / 4; i += 1024) s4[i] = make_uint4(0u, 0u, 0u, 0u);
    if (threadIdx.x < NCH) sc[threadIdx.x] = 0;
    __syncthreads();

    const int QE = HW / NPART;  // 65536 elements each of x, y
    const float4* px = (const float4*)(x + (size_t)b * HW + (size_t)q * QE);
    const float4* py = (const float4*)(y + (size_t)b * HW + (size_t)q * QE);
    for (int i = threadIdx.x; i < QE / 4; i += 1024) {
        float4 vx = px[i];
        float4 vy = py[i];
        unsigned int s;
        s = quantS(vx.x); atomicAdd(&sh[s >> 1], (1u << 22) + s);
        s = quantS(vy.x); atomicAdd(&sh[s >> 1], (unsigned int)(-(int)((1u << 22) + s)));
        s = quantS(vx.y); atomicAdd(&sh[s >> 1], (1u << 22) + s);
        s = quantS(vy.y); atomicAdd(&sh[s >> 1], (unsigned int)(-(int)((1u << 22) + s)));
        s = quantS(vx.z); atomicAdd(&sh[s >> 1], (1u << 22) + s);
        s = quantS(vy.z); atomicAdd(&sh[s >> 1], (unsigned int)(-(int)((1u << 22) + s)));
        s = quantS(vx.w); atomicAdd(&sh[s >> 1], (1u << 22) + s);
        s = quantS(vy.w); atomicAdd(&sh[s >> 1], (unsigned int)(-(int)((1u << 22) + s)));
    }
    __syncthreads();

    // vectorized write-out + per-chunk d sums (warp covers 128 bins = same chunk)
    unsigned int* g = g_part + (size_t)cta * KB;
    int lane = threadIdx.x & 31;
#pragma unroll
    for (int j = 0; j < 2; ++j) {
        int t4 = threadIdx.x + j * 1024;         // uint4 index (4 bins)
        uint4 v = s4[t4];
        ((uint4*)g)[t4] = v;
        int d = decD(v.x) + decD(v.y) + decD(v.z) + decD(v.w);
#pragma unroll
        for (int o = 16; o; o >>= 1) d += __shfl_down_sync(0xffffffffu, d, o);
        if (lane == 0 && d != 0) atomicAdd(&sc[t4 >> 7], d);
    }
    __syncthreads();
    if (threadIdx.x < NCH)
        g_csum[(b * NCH + threadIdx.x) * NPART + q] = sc[threadIdx.x];
}

// ---------------------------------------------------------------------------
// K2: fully parallel per-chunk scan, exact integer per-bin integral:
//   2^15 * integ_k = 4*Din + d_k*(4k+3) - 2*S_k
// grid = B*NCH, block = 128 (4 bins/thread, sums 4 partials)
// ---------------------------------------------------------------------------
__global__ void __launch_bounds__(128) k_scan(float* __restrict__ out) {
    int cta = blockIdx.x;
    int b = cta >> 4, ch = cta & (NCH - 1);
    int t = threadIdx.x, lane = t & 31, wid = t >> 5;

    int g0 = ch * CHB + t * 4;  // first of this thread's 4 bins
    const unsigned int* base = g_part + (size_t)b * NPART * KB;
    uint4 T  = *(const uint4*)(base + g0);
    uint4 T1 = *(const uint4*)(base + KB + g0);
    uint4 T2 = *(const uint4*)(base + 2 * KB + g0);
    uint4 T3 = *(const uint4*)(base + 3 * KB + g0);
    T.x += T1.x + T2.x + T3.x;
    T.y += T1.y + T2.y + T3.y;
    T.z += T1.z + T2.z + T3.z;
    T.w += T1.w + T2.w + T3.w;

    int d0 = decD(T.x), d1 = decD(T.y), d2 = decD(T.z), d3 = decD(T.w);
    int S0 = (int)T.x - (d0 << 22);
    int S1 = (int)T.y - (d1 << 22);
    int S2 = (int)T.z - (d2 << 22);
    int S3 = (int)T.w - (d3 << 22);
    int tsum = d0 + d1 + d2 + d3;

    // carry = sum of earlier chunks' d totals (parallel: one int4 per lane)
    int c4 = 0;
    if (lane < ch) {
        int4 cs = *(const int4*)&g_csum[(b * NCH + lane) * NPART];
        c4 = cs.x + cs.y + cs.z + cs.w;
    }
#pragma unroll
    for (int o = 8; o; o >>= 1) c4 += __shfl_down_sync(0xffffffffu, c4, o);
    int carry = __shfl_sync(0xffffffffu, c4, 0);

    // block exclusive scan of per-thread tsum (128 threads = 4 warps)
    int s = tsum;
#pragma unroll
    for (int o = 1; o < 32; o <<= 1) {
        int u = __shfl_up_sync(0xffffffffu, s, o);
        if (lane >= o) s += u;
    }
    __shared__ int wt[4];
    if (lane == 31) wt[wid] = s;
    __syncthreads();
    if (t < 4) {
        int w = wt[t];
#pragma unroll
        for (int o = 1; o < 4; o <<= 1) {
            int u = __shfl_up_sync(0x0000000fu, w, o);
            if (t >= o) w += u;
        }
        wt[t] = w;
    }
    __syncthreads();
    long long Din = (long long)carry + (wid ? wt[wid - 1] : 0) + (s - tsum);

    long long acc = 0, v;
    v = 4 * Din + (long long)d0 * (4LL * g0 + 3) - 2LL * S0;  acc += v < 0 ? -v : v;  Din += d0;
    v = 4 * Din + (long long)d1 * (4LL * g0 + 7) - 2LL * S1;  acc += v < 0 ? -v : v;  Din += d1;
    v = 4 * Din + (long long)d2 * (4LL * g0 + 11) - 2LL * S2; acc += v < 0 ? -v : v;  Din += d2;
    v = 4 * Din + (long long)d3 * (4LL * g0 + 15) - 2LL * S3; acc += v < 0 ? -v : v;

    // block reduce acc (int64)
#pragma unroll
    for (int o = 16; o; o >>= 1) acc += __shfl_down_sync(0xffffffffu, acc, o);
    __shared__ long long wr[4];
    if (lane == 0) wr[wid] = acc;
    __syncthreads();
    if (t == 0) {
        acc = wr[0] + wr[1] + wr[2] + wr[3];
        atomicAdd(out, (float)((double)acc * (1.0 / 32768.0)));
    }
}

extern "C" void kernel_launch(void* const* d_in, const int* in_sizes, int n_in,
                              void* d_out, int out_size) {
    const float* x = (const float*)d_in[0];
    const float* y = (const float*)d_in[1];
    int B = in_sizes[0] / HW;
    if (B > MAXB) B = MAXB;

    cudaMemsetAsync(d_out, 0, sizeof(float));
    k_hist<<<NPART * B, 1024>>>(x, y);
    k_scan<<<B * NCH, 128>>>((float*)d_out);
}